// round 1
// baseline (speedup 1.0000x reference)
#include <cuda_runtime.h>
#include <math.h>

#define BATCH   8
#define SEQ     1024
#define IN_DIM  64
#define D_MODEL 256
#define D_INNER 512
#define D_STATE 16
#define D_CONV  4
#define DT_RANK 16
#define N_LAYERS 4
#define BL (BATCH*SEQ)            // 8192 rows

// ---------------- scratch (static device globals; no runtime alloc) --------
__device__ float g_h   [BL * D_MODEL];        //  8 MB  (layer input / LN out)
__device__ float g_xz  [BL * 2 * D_INNER];    // 32 MB  (xh | z)
__device__ float g_xc  [BL * D_INNER];        // 16 MB
__device__ float g_xdbl[BL * 48];             // 1.5MB  (dtr|B|C)
__device__ float g_dt  [BL * D_INNER];        // 16 MB  (softplus'd dt)
__device__ float g_y   [BL * D_INNER];        // 16 MB
__device__ float g_ob  [BL * D_MODEL];        //  8 MB  (pre-LN gemm out)

// ---------------- generic NT SGEMM: C[M,N] = A[M,K] * B[N,K]^T (+bias,act) -
// BM=128 BN=64 BK=16, TM=8 TN=4, 256 threads.
// ACT: 0 = none, 1 = softplus (for dt path)
template<int ACT>
__global__ void __launch_bounds__(256)
gemm_nt_kernel(const float* __restrict__ A, int lda,
               const float* __restrict__ B, int ldb,
               const float* __restrict__ bias,
               float* __restrict__ C, int ldc,
               int M, int N, int K)
{
    constexpr int BM = 128, BN = 64, BK = 16, TM = 8, TN = 4;
    __shared__ float As[BK][BM];
    __shared__ float Bs[BK][BN];

    const int tid = threadIdx.x;
    const int tx  = tid & 15;        // N direction (16 * TN = 64)
    const int ty  = tid >> 4;        // M direction (16 * TM = 128)
    const int m0  = blockIdx.y * BM;
    const int n0  = blockIdx.x * BN;

    float acc[TM][TN];
    #pragma unroll
    for (int i = 0; i < TM; i++)
        #pragma unroll
        for (int j = 0; j < TN; j++) acc[i][j] = 0.f;

    for (int k0 = 0; k0 < K; k0 += BK) {
        // load A tile (BM x BK = 2048 floats, 8 per thread)
        #pragma unroll
        for (int i = 0; i < 8; i++) {
            int idx = tid + i * 256;
            int r = idx >> 4, c = idx & 15;
            As[c][r] = A[(long)(m0 + r) * lda + k0 + c];
        }
        // load B tile (BN x BK = 1024 floats, 4 per thread); guard N edge
        #pragma unroll
        for (int i = 0; i < 4; i++) {
            int idx = tid + i * 256;
            int r = idx >> 4, c = idx & 15;
            float v = 0.f;
            if (n0 + r < N) v = B[(long)(n0 + r) * ldb + k0 + c];
            Bs[c][r] = v;
        }
        __syncthreads();

        #pragma unroll
        for (int kk = 0; kk < BK; kk++) {
            float ra[TM], rb[TN];
            #pragma unroll
            for (int i = 0; i < TM; i++) ra[i] = As[kk][ty * TM + i];
            #pragma unroll
            for (int j = 0; j < TN; j++) rb[j] = Bs[kk][tx * TN + j];
            #pragma unroll
            for (int i = 0; i < TM; i++)
                #pragma unroll
                for (int j = 0; j < TN; j++)
                    acc[i][j] += ra[i] * rb[j];
        }
        __syncthreads();
    }

    #pragma unroll
    for (int i = 0; i < TM; i++) {
        int m = m0 + ty * TM + i;
        #pragma unroll
        for (int j = 0; j < TN; j++) {
            int n = n0 + tx * TN + j;
            if (n < N) {
                float v = acc[i][j];
                if (bias) v += bias[n];
                if (ACT == 1) {                       // softplus
                    v = (v > 20.f) ? v : log1pf(__expf(v));
                }
                C[(long)m * ldc + n] = v;
            }
        }
    }
}

// ---------------- causal depthwise conv (D_CONV=4) + SiLU ------------------
__global__ void __launch_bounds__(256)
conv_silu_kernel(const float* __restrict__ xz,   // (BL, 1024): xh = [:512]
                 const float* __restrict__ cw,   // (512, 4)
                 const float* __restrict__ cb,   // (512)
                 float* __restrict__ xc)         // (BL, 512)
{
    int idx = blockIdx.x * 256 + threadIdx.x;    // over BL*512
    int d  = idx & (D_INNER - 1);
    int bl = idx >> 9;
    int l  = bl & (SEQ - 1);
    int b0 = bl - l;                             // b*SEQ

    float acc = cb[d];
    #pragma unroll
    for (int k = 0; k < D_CONV; k++) {
        int ls = l - (D_CONV - 1) + k;
        if (ls >= 0)
            acc += xz[(long)(b0 + ls) * (2 * D_INNER) + d] * cw[d * D_CONV + k];
    }
    xc[idx] = acc / (1.f + __expf(-acc));        // silu
}

// ---------------- selective scan (fused gate + skip) ------------------------
// Thread layout: 256 threads = 16 channels x 16 states. Half-warp reduces over
// the 16 states via shfl_xor. Grid: (32 d-blocks, 8 batches).
__global__ void __launch_bounds__(256)
scan_kernel(const float* __restrict__ xdbl,  // (BL,48): [16:32]=Bm [32:48]=Cm
            const float* __restrict__ dt,    // (BL,512) softplus'd
            const float* __restrict__ xc,    // (BL,512)
            const float* __restrict__ xz,    // (BL,1024): z at +512
            const float* __restrict__ A_log, // (512,16)
            const float* __restrict__ Dp,    // (512)
            float* __restrict__ y)           // (BL,512)
{
    const int b   = blockIdx.y;
    const int tid = threadIdx.x;
    const int hw  = tid >> 4;                // channel within block (0..15)
    const int n   = tid & 15;                // state index
    const int d   = blockIdx.x * 16 + hw;

    const float A    = -__expf(A_log[d * D_STATE + n]);
    const float Dval = Dp[d];

    const float* pdt = dt   + (long)b * SEQ * D_INNER + d;
    const float* pxc = xc   + (long)b * SEQ * D_INNER + d;
    const float* pz  = xz   + (long)b * SEQ * 2 * D_INNER + D_INNER + d;
    const float* pB  = xdbl + (long)b * SEQ * 48 + DT_RANK + n;
    const float* pC  = pB + D_STATE;
    float*       py  = y    + (long)b * SEQ * D_INNER + d;

    float h = 0.f;
    #pragma unroll 2
    for (int t = 0; t < SEQ; t++) {
        float dtv = __ldg(pdt);
        float xcv = __ldg(pxc);
        float bv  = __ldg(pB);
        float cv  = __ldg(pC);

        float dA = __expf(dtv * A);
        h = fmaf(dA, h, dtv * bv * xcv);

        float p = h * cv;
        p += __shfl_xor_sync(0xffffffffu, p, 1);
        p += __shfl_xor_sync(0xffffffffu, p, 2);
        p += __shfl_xor_sync(0xffffffffu, p, 4);
        p += __shfl_xor_sync(0xffffffffu, p, 8);

        if (n == 0) {
            float zv  = __ldg(pz);
            float sil = zv / (1.f + __expf(-zv));
            *py = (p + Dval * xcv) * sil;
        }
        pdt += D_INNER; pxc += D_INNER; pz += 2 * D_INNER;
        pB += 48; pC += 48; py += D_INNER;
    }
}

// ---------------- layernorm over D_MODEL=256 --------------------------------
__device__ __forceinline__ float block_sum256(float v, float* sm)
{
    #pragma unroll
    for (int o = 16; o; o >>= 1) v += __shfl_xor_sync(0xffffffffu, v, o);
    __syncthreads();                     // protect prior sm use
    if ((threadIdx.x & 31) == 0) sm[threadIdx.x >> 5] = v;
    __syncthreads();
    float tot = 0.f;
    #pragma unroll
    for (int j = 0; j < 8; j++) tot += sm[j];
    return tot;
}

__global__ void __launch_bounds__(256)
ln_kernel(const float* __restrict__ in, const float* __restrict__ g,
          const float* __restrict__ b, float* __restrict__ out)
{
    __shared__ float sm[8];
    const int row = blockIdx.x;
    const int i   = threadIdx.x;
    float v    = in[(long)row * D_MODEL + i];
    float mean = block_sum256(v, sm) * (1.f / D_MODEL);
    float dv   = v - mean;
    float var  = block_sum256(dv * dv, sm) * (1.f / D_MODEL);
    out[(long)row * D_MODEL + i] = dv * rsqrtf(var + 1e-5f) * g[i] + b[i];
}

// ---------------- mean pool over L + linear head -----------------------------
__global__ void __launch_bounds__(1024)
final_kernel(const float* __restrict__ h, const float* __restrict__ Wf,
             const float* __restrict__ bf, float* __restrict__ out)
{
    __shared__ float red[1024];
    __shared__ float sm[8];
    const int b   = blockIdx.x;
    const int tid = threadIdx.x;
    const int d   = tid & 255;
    const int lc  = tid >> 8;            // 4 chunks of 256 steps

    float s = 0.f;
    for (int l = lc * 256; l < (lc + 1) * 256; l++)
        s += h[((long)b * SEQ + l) * D_MODEL + d];
    red[tid] = s;
    __syncthreads();

    if (tid < 256) {
        float tot = red[tid] + red[tid + 256] + red[tid + 512] + red[tid + 768];
        float val = tot * (1.f / SEQ) * Wf[d];
        #pragma unroll
        for (int o = 16; o; o >>= 1) val += __shfl_xor_sync(0xffffffffu, val, o);
        if ((tid & 31) == 0) sm[tid >> 5] = val;
    }
    __syncthreads();
    if (tid == 0) {
        float tot = 0.f;
        #pragma unroll
        for (int j = 0; j < 8; j++) tot += sm[j];
        out[b] = tot + bf[0];
    }
}

// ---------------- host orchestration ----------------------------------------
extern "C" void kernel_launch(void* const* d_in, const int* in_sizes, int n_in,
                              void* d_out, int out_size)
{
    const float* x      = (const float*)d_in[0];
    const float* Wp     = (const float*)d_in[1];
    const float* bp     = (const float*)d_in[2];
    const float* W_in   = (const float*)d_in[3];
    const float* conv_w = (const float*)d_in[4];
    const float* conv_b = (const float*)d_in[5];
    const float* W_x    = (const float*)d_in[6];
    const float* W_dt   = (const float*)d_in[7];
    const float* b_dt   = (const float*)d_in[8];
    const float* A_log  = (const float*)d_in[9];
    const float* Dp     = (const float*)d_in[10];
    const float* W_out  = (const float*)d_in[11];
    const float* ln_g   = (const float*)d_in[12];
    const float* ln_b   = (const float*)d_in[13];
    const float* Wf     = (const float*)d_in[14];
    const float* bf     = (const float*)d_in[15];
    float* out = (float*)d_out;

    float *h, *xz, *xc, *xdbl, *dtb, *y, *ob;
    cudaGetSymbolAddress((void**)&h,    g_h);
    cudaGetSymbolAddress((void**)&xz,   g_xz);
    cudaGetSymbolAddress((void**)&xc,   g_xc);
    cudaGetSymbolAddress((void**)&xdbl, g_xdbl);
    cudaGetSymbolAddress((void**)&dtb,  g_dt);
    cudaGetSymbolAddress((void**)&y,    g_y);
    cudaGetSymbolAddress((void**)&ob,   g_ob);

    const int GY = BL / 128;   // 64 M-tiles

    // input projection: h = x @ Wp^T + bp   (M=8192, N=256, K=64)
    gemm_nt_kernel<0><<<dim3(D_MODEL / 64, GY), 256>>>(
        x, IN_DIM, Wp, IN_DIM, bp, h, D_MODEL, BL, D_MODEL, IN_DIM);

    for (int l = 0; l < N_LAYERS; l++) {
        const float* Wi = W_in  + (long)l * 2 * D_INNER * D_MODEL;
        const float* cw = conv_w + (long)l * D_INNER * D_CONV;
        const float* cb = conv_b + (long)l * D_INNER;
        const float* Wx = W_x   + (long)l * 48 * D_INNER;
        const float* Wd = W_dt  + (long)l * D_INNER * DT_RANK;
        const float* bd = b_dt  + (long)l * D_INNER;
        const float* Al = A_log + (long)l * D_INNER * D_STATE;
        const float* Dl = Dp    + (long)l * D_INNER;
        const float* Wo = W_out + (long)l * D_MODEL * D_INNER;
        const float* lg = ln_g  + (long)l * D_MODEL;
        const float* lb = ln_b  + (long)l * D_MODEL;

        // xz = h @ W_in^T          (N=1024, K=256)
        gemm_nt_kernel<0><<<dim3(1024 / 64, GY), 256>>>(
            h, D_MODEL, Wi, D_MODEL, nullptr, xz, 2 * D_INNER,
            BL, 2 * D_INNER, D_MODEL);

        // xc = silu(conv(xh) + cb)
        conv_silu_kernel<<<BL * D_INNER / 256, 256>>>(xz, cw, cb, xc);

        // x_dbl = xc @ W_x^T       (N=48, K=512)
        gemm_nt_kernel<0><<<dim3(1, GY), 256>>>(
            xc, D_INNER, Wx, D_INNER, nullptr, xdbl, 48, BL, 48, D_INNER);

        // dt = softplus(dtr @ W_dt^T + b_dt)   (N=512, K=16, lda=48)
        gemm_nt_kernel<1><<<dim3(D_INNER / 64, GY), 256>>>(
            xdbl, 48, Wd, DT_RANK, bd, dtb, D_INNER, BL, D_INNER, DT_RANK);

        // selective scan + gate
        scan_kernel<<<dim3(D_INNER / 16, BATCH), 256>>>(
            xdbl, dtb, xc, xz, Al, Dl, y);

        // out = y @ W_out^T        (N=256, K=512)
        gemm_nt_kernel<0><<<dim3(D_MODEL / 64, GY), 256>>>(
            y, D_INNER, Wo, D_INNER, nullptr, ob, D_MODEL, BL, D_MODEL, D_INNER);

        // h = layernorm(out)
        ln_kernel<<<BL, 256>>>(ob, lg, lb, h);
    }

    final_kernel<<<BATCH, 1024>>>(h, Wf, bf, out);
}

// round 2
// speedup vs baseline: 1.1667x; 1.1667x over previous
#include <cuda_runtime.h>
#include <math.h>

#define BATCH   8
#define SEQ     1024
#define IN_DIM  64
#define D_MODEL 256
#define D_INNER 512
#define D_STATE 16
#define D_CONV  4
#define DT_RANK 16
#define N_LAYERS 4
#define BL (BATCH*SEQ)            // 8192 rows

// ---------------- scratch (static device globals; no runtime alloc) --------
__device__ float g_h   [BL * D_MODEL];
__device__ float g_xz  [BL * 2 * D_INNER];
__device__ float g_xc  [BL * D_INNER];
__device__ float g_xdbl[BL * 48];
__device__ float g_dt  [BL * D_INNER];
__device__ float g_y   [BL * D_INNER];
__device__ float g_ob  [BL * D_MODEL];

// ---------------- f32x2 helpers --------------------------------------------
__device__ __forceinline__ unsigned long long pk2dup(float a) {
    unsigned long long r;
    asm("mov.b64 %0, {%1, %1};" : "=l"(r) : "f"(a));
    return r;
}
__device__ __forceinline__ void fma2(unsigned long long& d,
                                     unsigned long long a, unsigned long long b) {
    asm("fma.rn.f32x2 %0, %1, %2, %0;" : "+l"(d) : "l"(a), "l"(b));
}
__device__ __forceinline__ float2 up2(unsigned long long v) {
    float2 o;
    asm("mov.b64 {%0, %1}, %2;" : "=f"(o.x), "=f"(o.y) : "l"(v));
    return o;
}

// ---------------- NT GEMM with f32x2 math, double-buffered smem -------------
// C[M,N] = A[M,K] * B[N,K]^T (+bias, +activation). ACT: 0=none, 1=softplus.
template<int BM, int BN, int BK, int TM, int TN, int ACT, bool NG>
__global__ void __launch_bounds__((BM/TM)*(BN/TN))
gemm2_kernel(const float* __restrict__ A, int lda,
             const float* __restrict__ B, int ldb,
             const float* __restrict__ bias,
             float* __restrict__ C, int ldc,
             int M, int N, int K)
{
    constexpr int THREADS = (BM/TM)*(BN/TN);
    constexpr int LAV = (BM*BK)/(4*THREADS);     // float4 A loads / thread
    constexpr int LBV = (BN*BK)/(4*THREADS);
    static_assert(LAV >= 1 && LBV >= 1, "tile too small");
    static_assert(BK % 4 == 0 && TM % 4 == 0 && TN % 4 == 0, "vec req");

    __shared__ __align__(16) float As[2][BK][BM];
    __shared__ __align__(16) float Bs[2][BK][BN];

    const int tid = threadIdx.x;
    const int tx  = tid % (BN/TN);
    const int ty  = tid / (BN/TN);
    const int m0  = blockIdx.y * BM;
    const int n0  = blockIdx.x * BN;

    unsigned long long acc[TM][TN/2];
    #pragma unroll
    for (int i = 0; i < TM; i++)
        #pragma unroll
        for (int j = 0; j < TN/2; j++) acc[i][j] = 0ull;

    float4 vA[LAV], vB[LBV];

    auto loadA = [&](int k0) {
        #pragma unroll
        for (int i = 0; i < LAV; i++) {
            int idx = tid + i * THREADS;
            int r = idx / (BK/4), cq = idx % (BK/4);
            vA[i] = *(const float4*)&A[(long)(m0 + r) * lda + k0 + cq*4];
        }
    };
    auto loadB = [&](int k0) {
        #pragma unroll
        for (int i = 0; i < LBV; i++) {
            int idx = tid + i * THREADS;
            int r = idx / (BK/4), cq = idx % (BK/4);
            if (!NG || (n0 + r) < N)
                vB[i] = *(const float4*)&B[(long)(n0 + r) * ldb + k0 + cq*4];
            else
                vB[i] = make_float4(0.f, 0.f, 0.f, 0.f);
        }
    };
    auto stage = [&](int s) {
        #pragma unroll
        for (int i = 0; i < LAV; i++) {
            int idx = tid + i * THREADS;
            int r = idx / (BK/4), cq = idx % (BK/4);
            As[s][cq*4+0][r] = vA[i].x;  As[s][cq*4+1][r] = vA[i].y;
            As[s][cq*4+2][r] = vA[i].z;  As[s][cq*4+3][r] = vA[i].w;
        }
        #pragma unroll
        for (int i = 0; i < LBV; i++) {
            int idx = tid + i * THREADS;
            int r = idx / (BK/4), cq = idx % (BK/4);
            Bs[s][cq*4+0][r] = vB[i].x;  Bs[s][cq*4+1][r] = vB[i].y;
            Bs[s][cq*4+2][r] = vB[i].z;  Bs[s][cq*4+3][r] = vB[i].w;
        }
    };

    loadA(0); loadB(0); stage(0);
    __syncthreads();

    int s = 0;
    for (int k0 = 0; k0 < K; k0 += BK) {
        bool has_next = (k0 + BK) < K;
        if (has_next) { loadA(k0 + BK); loadB(k0 + BK); }

        #pragma unroll
        for (int kk = 0; kk < BK; kk++) {
            float a[TM];
            #pragma unroll
            for (int i = 0; i < TM; i += 4)
                *(float4*)&a[i] = *(const float4*)&As[s][kk][ty*TM + i];
            unsigned long long a2[TM];
            #pragma unroll
            for (int i = 0; i < TM; i++) a2[i] = pk2dup(a[i]);

            unsigned long long b2[TN/2];
            #pragma unroll
            for (int j = 0; j < TN/2; j += 2) {
                ulonglong2 tv = *(const ulonglong2*)&Bs[s][kk][tx*TN + 2*j];
                b2[j] = tv.x;  b2[j+1] = tv.y;
            }

            #pragma unroll
            for (int i = 0; i < TM; i++)
                #pragma unroll
                for (int j = 0; j < TN/2; j++)
                    fma2(acc[i][j], a2[i], b2[j]);
        }

        if (has_next) {
            stage(s ^ 1);
            __syncthreads();
            s ^= 1;
        }
    }

    #pragma unroll
    for (int i = 0; i < TM; i++) {
        int m = m0 + ty*TM + i;
        #pragma unroll
        for (int j = 0; j < TN/2; j++) {
            float2 v = up2(acc[i][j]);
            int n = n0 + tx*TN + 2*j;
            float x0 = v.x, x1 = v.y;
            if (bias) {
                if (!NG || n   < N) x0 += bias[n];
                if (!NG || n+1 < N) x1 += bias[n+1];
            }
            if (ACT == 1) {
                x0 = (x0 > 20.f) ? x0 : log1pf(__expf(x0));
                x1 = (x1 > 20.f) ? x1 : log1pf(__expf(x1));
            }
            if (!NG || n   < N) C[(long)m*ldc + n  ] = x0;
            if (!NG || n+1 < N) C[(long)m*ldc + n+1] = x1;
        }
    }
}

// ---------------- causal depthwise conv (D_CONV=4) + SiLU ------------------
__global__ void __launch_bounds__(256)
conv_silu_kernel(const float* __restrict__ xz,
                 const float* __restrict__ cw,
                 const float* __restrict__ cb,
                 float* __restrict__ xc)
{
    int idx = blockIdx.x * 256 + threadIdx.x;
    int d  = idx & (D_INNER - 1);
    int bl = idx >> 9;
    int l  = bl & (SEQ - 1);
    int b0 = bl - l;

    float acc = cb[d];
    #pragma unroll
    for (int k = 0; k < D_CONV; k++) {
        int ls = l - (D_CONV - 1) + k;
        if (ls >= 0)
            acc += xz[(long)(b0 + ls) * (2*D_INNER) + d] * cw[d*D_CONV + k];
    }
    xc[idx] = acc / (1.f + __expf(-acc));
}

// ---------------- selective scan v2: 4 states / thread ---------------------
// 64 threads: 16 channels x 4 state-groups. Grid (D_INNER/16, BATCH).
__global__ void __launch_bounds__(64)
scan2_kernel(const float* __restrict__ xdbl,   // (BL,48): B @16, C @32
             const float* __restrict__ dt,     // (BL,512) softplus'd
             const float* __restrict__ xc,     // (BL,512)
             const float* __restrict__ xz,     // (BL,1024): z at +512
             const float* __restrict__ A_log,  // (512,16)
             const float* __restrict__ Dp,     // (512)
             float* __restrict__ y)            // (BL,512)
{
    const int b    = blockIdx.y;
    const int tid  = threadIdx.x;
    const int lane = tid & 31;
    const int w    = tid >> 5;           // warp 0/1
    const int q    = lane & 3;           // state group
    const int c    = lane >> 2;          // channel within warp (0..7)
    const int d    = blockIdx.x * 16 + w * 8 + c;
    const int n0   = q * 4;

    const float A0 = -__expf(A_log[d*D_STATE + n0 + 0]);
    const float A1 = -__expf(A_log[d*D_STATE + n0 + 1]);
    const float A2 = -__expf(A_log[d*D_STATE + n0 + 2]);
    const float A3 = -__expf(A_log[d*D_STATE + n0 + 3]);
    const float Dval = Dp[d];

    const float* pdt = dt   + (long)b*SEQ*D_INNER + d;
    const float* pxc = xc   + (long)b*SEQ*D_INNER + d;
    const float* pz  = xz   + (long)b*SEQ*2*D_INNER + D_INNER + d;
    const float* pbc = xdbl + (long)b*SEQ*48;
    float*       py  = y    + (long)b*SEQ*D_INNER + blockIdx.x*16 + w*8;

    float h0 = 0.f, h1 = 0.f, h2 = 0.f, h3 = 0.f;

    #pragma unroll 2
    for (int t = 0; t < SEQ; t++) {
        float dtv = __ldg(pdt + (long)t * D_INNER);
        float xcv = __ldg(pxc + (long)t * D_INNER);
        float4 Bv = __ldg((const float4*)(pbc + (long)t*48 + 16 + n0));
        float4 Cv = __ldg((const float4*)(pbc + (long)t*48 + 32 + n0));

        float u = dtv * xcv;
        h0 = fmaf(__expf(dtv * A0), h0, u * Bv.x);
        h1 = fmaf(__expf(dtv * A1), h1, u * Bv.y);
        h2 = fmaf(__expf(dtv * A2), h2, u * Bv.z);
        h3 = fmaf(__expf(dtv * A3), h3, u * Bv.w);

        float p = h0*Cv.x + h1*Cv.y + h2*Cv.z + h3*Cv.w;
        p += __shfl_xor_sync(0xffffffffu, p, 1);
        p += __shfl_xor_sync(0xffffffffu, p, 2);

        float yv = 0.f;
        if (q == 0) {
            float zv = __ldg(pz + (long)t * 2 * D_INNER);
            yv = (p + Dval * xcv) * (zv / (1.f + __expf(-zv)));
        }
        yv = __shfl_sync(0xffffffffu, yv, (lane & 7) * 4);
        if (lane < 8)
            py[(long)t * D_INNER + lane] = yv;
    }
}

// ---------------- layernorm over D_MODEL=256 --------------------------------
__device__ __forceinline__ float block_sum256(float v, float* sm)
{
    #pragma unroll
    for (int o = 16; o; o >>= 1) v += __shfl_xor_sync(0xffffffffu, v, o);
    __syncthreads();
    if ((threadIdx.x & 31) == 0) sm[threadIdx.x >> 5] = v;
    __syncthreads();
    float tot = 0.f;
    #pragma unroll
    for (int j = 0; j < 8; j++) tot += sm[j];
    return tot;
}

__global__ void __launch_bounds__(256)
ln_kernel(const float* __restrict__ in, const float* __restrict__ g,
          const float* __restrict__ b, float* __restrict__ out)
{
    __shared__ float sm[8];
    const int row = blockIdx.x;
    const int i   = threadIdx.x;
    float v    = in[(long)row * D_MODEL + i];
    float mean = block_sum256(v, sm) * (1.f / D_MODEL);
    float dv   = v - mean;
    float var  = block_sum256(dv * dv, sm) * (1.f / D_MODEL);
    out[(long)row * D_MODEL + i] = dv * rsqrtf(var + 1e-5f) * g[i] + b[i];
}

// ---------------- mean pool over L + linear head -----------------------------
__global__ void __launch_bounds__(1024)
final_kernel(const float* __restrict__ h, const float* __restrict__ Wf,
             const float* __restrict__ bf, float* __restrict__ out)
{
    __shared__ float red[1024];
    __shared__ float sm[8];
    const int b   = blockIdx.x;
    const int tid = threadIdx.x;
    const int d   = tid & 255;
    const int lc  = tid >> 8;

    float s = 0.f;
    for (int l = lc * 256; l < (lc + 1) * 256; l++)
        s += h[((long)b * SEQ + l) * D_MODEL + d];
    red[tid] = s;
    __syncthreads();

    if (tid < 256) {
        float tot = red[tid] + red[tid + 256] + red[tid + 512] + red[tid + 768];
        float val = tot * (1.f / SEQ) * Wf[d];
        #pragma unroll
        for (int o = 16; o; o >>= 1) val += __shfl_xor_sync(0xffffffffu, val, o);
        if ((tid & 31) == 0) sm[tid >> 5] = val;
    }
    __syncthreads();
    if (tid == 0) {
        float tot = 0.f;
        #pragma unroll
        for (int j = 0; j < 8; j++) tot += sm[j];
        out[b] = tot + bf[0];
    }
}

// ---------------- host orchestration ----------------------------------------
extern "C" void kernel_launch(void* const* d_in, const int* in_sizes, int n_in,
                              void* d_out, int out_size)
{
    const float* x      = (const float*)d_in[0];
    const float* Wp     = (const float*)d_in[1];
    const float* bp     = (const float*)d_in[2];
    const float* W_in   = (const float*)d_in[3];
    const float* conv_w = (const float*)d_in[4];
    const float* conv_b = (const float*)d_in[5];
    const float* W_x    = (const float*)d_in[6];
    const float* W_dt   = (const float*)d_in[7];
    const float* b_dt   = (const float*)d_in[8];
    const float* A_log  = (const float*)d_in[9];
    const float* Dp     = (const float*)d_in[10];
    const float* W_out  = (const float*)d_in[11];
    const float* ln_g   = (const float*)d_in[12];
    const float* ln_b   = (const float*)d_in[13];
    const float* Wf     = (const float*)d_in[14];
    const float* bf     = (const float*)d_in[15];
    float* out = (float*)d_out;

    float *h, *xz, *xc, *xdbl, *dtb, *y, *ob;
    cudaGetSymbolAddress((void**)&h,    g_h);
    cudaGetSymbolAddress((void**)&xz,   g_xz);
    cudaGetSymbolAddress((void**)&xc,   g_xc);
    cudaGetSymbolAddress((void**)&xdbl, g_xdbl);
    cudaGetSymbolAddress((void**)&dtb,  g_dt);
    cudaGetSymbolAddress((void**)&y,    g_y);
    cudaGetSymbolAddress((void**)&ob,   g_ob);

    // input projection: h = x @ Wp^T + bp   (M=8192, N=256, K=64)
    gemm2_kernel<128,64,16,8,4,0,false><<<dim3(D_MODEL/64, BL/128), 256>>>(
        x, IN_DIM, Wp, IN_DIM, bp, h, D_MODEL, BL, D_MODEL, IN_DIM);

    for (int l = 0; l < N_LAYERS; l++) {
        const float* Wi = W_in  + (long)l * 2*D_INNER * D_MODEL;
        const float* cw = conv_w + (long)l * D_INNER * D_CONV;
        const float* cb = conv_b + (long)l * D_INNER;
        const float* Wx = W_x   + (long)l * 48 * D_INNER;
        const float* Wd = W_dt  + (long)l * D_INNER * DT_RANK;
        const float* bd = b_dt  + (long)l * D_INNER;
        const float* Al = A_log + (long)l * D_INNER * D_STATE;
        const float* Dl = Dp    + (long)l * D_INNER;
        const float* Wo = W_out + (long)l * D_MODEL * D_INNER;
        const float* lg = ln_g  + (long)l * D_MODEL;
        const float* lb = ln_b  + (long)l * D_MODEL;

        // xz = h @ W_in^T   (M=8192, N=1024, K=256)
        gemm2_kernel<128,128,16,8,8,0,false><<<dim3(1024/128, BL/128), 256>>>(
            h, D_MODEL, Wi, D_MODEL, nullptr, xz, 2*D_INNER,
            BL, 2*D_INNER, D_MODEL);

        // xc = silu(conv(xh) + cb)
        conv_silu_kernel<<<BL*D_INNER/256, 256>>>(xz, cw, cb, xc);

        // x_dbl = xc @ W_x^T  (N=48, K=512) — BM=64 for 128 blocks
        gemm2_kernel<64,64,16,4,4,0,true><<<dim3(1, BL/64), 256>>>(
            xc, D_INNER, Wx, D_INNER, nullptr, xdbl, 48, BL, 48, D_INNER);

        // dt = softplus(dtr @ W_dt^T + b_dt)   (N=512, K=16)
        gemm2_kernel<128,64,16,8,4,1,false><<<dim3(D_INNER/64, BL/128), 256>>>(
            xdbl, 48, Wd, DT_RANK, bd, dtb, D_INNER, BL, D_INNER, DT_RANK);

        // selective scan + gate
        scan2_kernel<<<dim3(D_INNER/16, BATCH), 64>>>(
            xdbl, dtb, xc, xz, Al, Dl, y);

        // out = y @ W_out^T  (N=256, K=512)
        gemm2_kernel<128,64,16,8,4,0,false><<<dim3(D_MODEL/64, BL/128), 256>>>(
            y, D_INNER, Wo, D_INNER, nullptr, ob, D_MODEL, BL, D_MODEL, D_INNER);

        // h = layernorm(out)
        ln_kernel<<<BL, 256>>>(ob, lg, lb, h);
    }

    final_kernel<<<BATCH, 1024>>>(h, Wf, bf, out);
}

// round 3
// speedup vs baseline: 1.5286x; 1.3102x over previous
#include <cuda_runtime.h>
#include <math.h>

#define BATCH   8
#define SEQ     1024
#define IN_DIM  64
#define D_MODEL 256
#define D_INNER 512
#define D_STATE 16
#define D_CONV  4
#define DT_RANK 16
#define N_LAYERS 4
#define BL (BATCH*SEQ)            // 8192 rows

// ---------------- scratch (static device globals; no runtime alloc) --------
__device__ float g_h   [BL * D_MODEL];
__device__ float g_xz  [BL * 2 * D_INNER];
__device__ float g_xc  [BL * D_INNER];
__device__ float g_xdbl[BL * 48];
__device__ float g_dt  [BL * D_INNER];
__device__ float g_y   [BL * D_INNER];
__device__ float g_ob  [BL * D_MODEL];

// ---------------- f32x2 helpers --------------------------------------------
__device__ __forceinline__ unsigned long long pk2dup(float a) {
    unsigned long long r;
    asm("mov.b64 %0, {%1, %1};" : "=l"(r) : "f"(a));
    return r;
}
__device__ __forceinline__ void fma2(unsigned long long& d,
                                     unsigned long long a, unsigned long long b) {
    asm("fma.rn.f32x2 %0, %1, %2, %0;" : "+l"(d) : "l"(a), "l"(b));
}
__device__ __forceinline__ float2 up2(unsigned long long v) {
    float2 o;
    asm("mov.b64 {%0, %1}, %2;" : "=f"(o.x), "=f"(o.y) : "l"(v));
    return o;
}

// ---------------- NT GEMM with f32x2 math, double-buffered smem -------------
// C[M,N] = A[M,K] * B[N,K]^T (+bias, +activation). ACT: 0=none, 1=softplus.
template<int BM, int BN, int BK, int TM, int TN, int ACT, bool NG>
__global__ void __launch_bounds__((BM/TM)*(BN/TN))
gemm2_kernel(const float* __restrict__ A, int lda,
             const float* __restrict__ B, int ldb,
             const float* __restrict__ bias,
             float* __restrict__ C, int ldc,
             int M, int N, int K)
{
    constexpr int THREADS = (BM/TM)*(BN/TN);
    constexpr int LAV = (BM*BK)/(4*THREADS);
    constexpr int LBV = (BN*BK)/(4*THREADS);
    static_assert(LAV >= 1 && LBV >= 1, "tile too small");
    static_assert(BK % 4 == 0 && TM % 4 == 0 && TN % 4 == 0, "vec req");

    __shared__ __align__(16) float As[2][BK][BM];
    __shared__ __align__(16) float Bs[2][BK][BN];

    const int tid = threadIdx.x;
    const int tx  = tid % (BN/TN);
    const int ty  = tid / (BN/TN);
    const int m0  = blockIdx.y * BM;
    const int n0  = blockIdx.x * BN;

    unsigned long long acc[TM][TN/2];
    #pragma unroll
    for (int i = 0; i < TM; i++)
        #pragma unroll
        for (int j = 0; j < TN/2; j++) acc[i][j] = 0ull;

    float4 vA[LAV], vB[LBV];

    auto loadA = [&](int k0) {
        #pragma unroll
        for (int i = 0; i < LAV; i++) {
            int idx = tid + i * THREADS;
            int r = idx / (BK/4), cq = idx % (BK/4);
            vA[i] = *(const float4*)&A[(long)(m0 + r) * lda + k0 + cq*4];
        }
    };
    auto loadB = [&](int k0) {
        #pragma unroll
        for (int i = 0; i < LBV; i++) {
            int idx = tid + i * THREADS;
            int r = idx / (BK/4), cq = idx % (BK/4);
            if (!NG || (n0 + r) < N)
                vB[i] = *(const float4*)&B[(long)(n0 + r) * ldb + k0 + cq*4];
            else
                vB[i] = make_float4(0.f, 0.f, 0.f, 0.f);
        }
    };
    auto stage = [&](int s) {
        #pragma unroll
        for (int i = 0; i < LAV; i++) {
            int idx = tid + i * THREADS;
            int r = idx / (BK/4), cq = idx % (BK/4);
            As[s][cq*4+0][r] = vA[i].x;  As[s][cq*4+1][r] = vA[i].y;
            As[s][cq*4+2][r] = vA[i].z;  As[s][cq*4+3][r] = vA[i].w;
        }
        #pragma unroll
        for (int i = 0; i < LBV; i++) {
            int idx = tid + i * THREADS;
            int r = idx / (BK/4), cq = idx % (BK/4);
            Bs[s][cq*4+0][r] = vB[i].x;  Bs[s][cq*4+1][r] = vB[i].y;
            Bs[s][cq*4+2][r] = vB[i].z;  Bs[s][cq*4+3][r] = vB[i].w;
        }
    };

    loadA(0); loadB(0); stage(0);
    __syncthreads();

    int s = 0;
    for (int k0 = 0; k0 < K; k0 += BK) {
        bool has_next = (k0 + BK) < K;
        if (has_next) { loadA(k0 + BK); loadB(k0 + BK); }

        #pragma unroll
        for (int kk = 0; kk < BK; kk++) {
            float a[TM];
            #pragma unroll
            for (int i = 0; i < TM; i += 4)
                *(float4*)&a[i] = *(const float4*)&As[s][kk][ty*TM + i];
            unsigned long long a2[TM];
            #pragma unroll
            for (int i = 0; i < TM; i++) a2[i] = pk2dup(a[i]);

            unsigned long long b2[TN/2];
            #pragma unroll
            for (int j = 0; j < TN/2; j += 2) {
                ulonglong2 tv = *(const ulonglong2*)&Bs[s][kk][tx*TN + 2*j];
                b2[j] = tv.x;  b2[j+1] = tv.y;
            }

            #pragma unroll
            for (int i = 0; i < TM; i++)
                #pragma unroll
                for (int j = 0; j < TN/2; j++)
                    fma2(acc[i][j], a2[i], b2[j]);
        }

        if (has_next) {
            stage(s ^ 1);
            __syncthreads();
            s ^= 1;
        }
    }

    #pragma unroll
    for (int i = 0; i < TM; i++) {
        int m = m0 + ty*TM + i;
        #pragma unroll
        for (int j = 0; j < TN/2; j++) {
            float2 v = up2(acc[i][j]);
            int n = n0 + tx*TN + 2*j;
            float x0 = v.x, x1 = v.y;
            if (bias) {
                if (!NG || n   < N) x0 += bias[n];
                if (!NG || n+1 < N) x1 += bias[n+1];
            }
            if (ACT == 1) {
                x0 = (x0 > 20.f) ? x0 : log1pf(__expf(x0));
                x1 = (x1 > 20.f) ? x1 : log1pf(__expf(x1));
            }
            if (!NG || n   < N) C[(long)m*ldc + n  ] = x0;
            if (!NG || n+1 < N) C[(long)m*ldc + n+1] = x1;
        }
    }
}

// ---------------- causal depthwise conv (D_CONV=4) + SiLU, float4 ----------
__global__ void __launch_bounds__(256)
conv_silu_kernel(const float* __restrict__ xz,   // (BL,1024): xh = [:512]
                 const float* __restrict__ cw,   // (512,4)
                 const float* __restrict__ cb,   // (512)
                 float* __restrict__ xc)         // (BL,512)
{
    int idx = blockIdx.x * 256 + threadIdx.x;    // over BL*128 float4s
    int dq = idx & 127;                          // d/4
    int bl = idx >> 7;
    int l  = bl & (SEQ - 1);
    int b0 = bl - l;
    int d  = dq * 4;

    float4 w0 = __ldg((const float4*)&cw[(d+0)*D_CONV]);
    float4 w1 = __ldg((const float4*)&cw[(d+1)*D_CONV]);
    float4 w2 = __ldg((const float4*)&cw[(d+2)*D_CONV]);
    float4 w3 = __ldg((const float4*)&cw[(d+3)*D_CONV]);
    float4 bv = __ldg((const float4*)&cb[d]);

    float a0 = bv.x, a1 = bv.y, a2 = bv.z, a3 = bv.w;
    #pragma unroll
    for (int k = 0; k < D_CONV; k++) {
        int ls = l - (D_CONV - 1) + k;
        if (ls >= 0) {
            float4 xv = __ldg((const float4*)&xz[(long)(b0+ls)*(2*D_INNER) + d]);
            float wk0 = (&w0.x)[k], wk1 = (&w1.x)[k];
            float wk2 = (&w2.x)[k], wk3 = (&w3.x)[k];
            a0 = fmaf(xv.x, wk0, a0);  a1 = fmaf(xv.y, wk1, a1);
            a2 = fmaf(xv.z, wk2, a2);  a3 = fmaf(xv.w, wk3, a3);
        }
    }
    float4 o;
    o.x = a0 / (1.f + __expf(-a0));
    o.y = a1 / (1.f + __expf(-a1));
    o.z = a2 / (1.f + __expf(-a2));
    o.w = a3 / (1.f + __expf(-a3));
    *(float4*)&xc[(long)bl * D_INNER + d] = o;
}

// ---------------- selective scan v3 ------------------------------------------
// 64 threads: 16 channels x 4 state-groups. Grid (D_INNER/16, BATCH).
// FAST path (A_n == -(n+1)): dA_n = r^(n+1), r = exp(-dt): 1 MUFU vs 4.
template<bool FAST>
__device__ __forceinline__ void scan_body(
    const float* pdt, const float* pxc, const float* pz, const float* pbc,
    float* py, int q, int lane,
    float A0, float A1, float A2, float A3, float Dval)
{
    float h0 = 0.f, h1 = 0.f, h2 = 0.f, h3 = 0.f;

    #pragma unroll 4
    for (int t = 0; t < SEQ; t++) {
        float  dtv = __ldg(pdt + (long)t * D_INNER);
        float  xcv = __ldg(pxc + (long)t * D_INNER);
        float4 Bv  = __ldg((const float4*)(pbc + (long)t*48 + 16 + q*4));
        float4 Cv  = __ldg((const float4*)(pbc + (long)t*48 + 32 + q*4));
        float  zv  = __ldg(pz  + (long)t * 2 * D_INNER);

        float dA0, dA1, dA2, dA3;
        if (FAST) {
            float r  = __expf(-dtv);
            float r2 = r * r;
            float r4 = r2 * r2;
            float p1;                       // r^(4q+1)
            if      (q == 0) p1 = r;
            else if (q == 1) p1 = r4 * r;
            else if (q == 2) p1 = (r4 * r4) * r;
            else             p1 = ((r4 * r4) * r4) * r;
            dA0 = p1; dA1 = p1 * r; dA2 = dA1 * r; dA3 = dA2 * r;
        } else {
            dA0 = __expf(dtv * A0);  dA1 = __expf(dtv * A1);
            dA2 = __expf(dtv * A2);  dA3 = __expf(dtv * A3);
        }

        float u = dtv * xcv;
        h0 = fmaf(dA0, h0, u * Bv.x);
        h1 = fmaf(dA1, h1, u * Bv.y);
        h2 = fmaf(dA2, h2, u * Bv.z);
        h3 = fmaf(dA3, h3, u * Bv.w);

        float p = fmaf(h3, Cv.w, fmaf(h2, Cv.z, fmaf(h1, Cv.y, h0 * Cv.x)));
        p += __shfl_xor_sync(0xffffffffu, p, 1);
        p += __shfl_xor_sync(0xffffffffu, p, 2);

        if (q == 0) {
            float sil = zv / (1.f + __expf(-zv));
            py[(long)t * D_INNER] = (p + Dval * xcv) * sil;
        }
    }
}

__global__ void __launch_bounds__(64)
scan3_kernel(const float* __restrict__ xdbl,   // (BL,48): B @16, C @32
             const float* __restrict__ dt,     // (BL,512) softplus'd
             const float* __restrict__ xc,     // (BL,512)
             const float* __restrict__ xz,     // (BL,1024): z at +512
             const float* __restrict__ A_log,  // (512,16)
             const float* __restrict__ Dp,     // (512)
             float* __restrict__ y)            // (BL,512)
{
    const int b    = blockIdx.y;
    const int tid  = threadIdx.x;
    const int lane = tid & 31;
    const int w    = tid >> 5;
    const int q    = lane & 3;
    const int c    = lane >> 2;
    const int d    = blockIdx.x * 16 + w * 8 + c;
    const int n0   = q * 4;

    const float A0 = -__expf(A_log[d*D_STATE + n0 + 0]);
    const float A1 = -__expf(A_log[d*D_STATE + n0 + 1]);
    const float A2 = -__expf(A_log[d*D_STATE + n0 + 2]);
    const float A3 = -__expf(A_log[d*D_STATE + n0 + 3]);
    const float Dval = Dp[d];

    // fast path iff A_n == -(n+1) to 1e-5 relative (true for the reference
    // init A_log = log(arange(1..16)); generic fallback otherwise)
    bool ok = (fabsf(A0 + (float)(n0+1)) <= 1e-5f * (n0+1)) &&
              (fabsf(A1 + (float)(n0+2)) <= 1e-5f * (n0+2)) &&
              (fabsf(A2 + (float)(n0+3)) <= 1e-5f * (n0+3)) &&
              (fabsf(A3 + (float)(n0+4)) <= 1e-5f * (n0+4));
    ok = __all_sync(0xffffffffu, ok);

    const float* pdt = dt   + (long)b*SEQ*D_INNER + d;
    const float* pxc = xc   + (long)b*SEQ*D_INNER + d;
    const float* pz  = xz   + (long)b*SEQ*2*D_INNER + D_INNER + d;
    const float* pbc = xdbl + (long)b*SEQ*48;
    float*       py  = y    + (long)b*SEQ*D_INNER + d;   // q==0 lanes store

    if (ok) scan_body<true >(pdt, pxc, pz, pbc, py, q, lane, A0, A1, A2, A3, Dval);
    else    scan_body<false>(pdt, pxc, pz, pbc, py, q, lane, A0, A1, A2, A3, Dval);
}

// ---------------- layernorm over D_MODEL=256 --------------------------------
__device__ __forceinline__ float block_sum256(float v, float* sm)
{
    #pragma unroll
    for (int o = 16; o; o >>= 1) v += __shfl_xor_sync(0xffffffffu, v, o);
    __syncthreads();
    if ((threadIdx.x & 31) == 0) sm[threadIdx.x >> 5] = v;
    __syncthreads();
    float tot = 0.f;
    #pragma unroll
    for (int j = 0; j < 8; j++) tot += sm[j];
    return tot;
}

__global__ void __launch_bounds__(256)
ln_kernel(const float* __restrict__ in, const float* __restrict__ g,
          const float* __restrict__ b, float* __restrict__ out)
{
    __shared__ float sm[8];
    const int row = blockIdx.x;
    const int i   = threadIdx.x;
    float v    = in[(long)row * D_MODEL + i];
    float mean = block_sum256(v, sm) * (1.f / D_MODEL);
    float dv   = v - mean;
    float var  = block_sum256(dv * dv, sm) * (1.f / D_MODEL);
    out[(long)row * D_MODEL + i] = dv * rsqrtf(var + 1e-5f) * g[i] + b[i];
}

// ---------------- mean pool over L + linear head -----------------------------
__global__ void __launch_bounds__(1024)
final_kernel(const float* __restrict__ h, const float* __restrict__ Wf,
             const float* __restrict__ bf, float* __restrict__ out)
{
    __shared__ float red[1024];
    __shared__ float sm[8];
    const int b   = blockIdx.x;
    const int tid = threadIdx.x;
    const int d   = tid & 255;
    const int lc  = tid >> 8;

    float s = 0.f;
    for (int l = lc * 256; l < (lc + 1) * 256; l++)
        s += h[((long)b * SEQ + l) * D_MODEL + d];
    red[tid] = s;
    __syncthreads();

    if (tid < 256) {
        float tot = red[tid] + red[tid + 256] + red[tid + 512] + red[tid + 768];
        float val = tot * (1.f / SEQ) * Wf[d];
        #pragma unroll
        for (int o = 16; o; o >>= 1) val += __shfl_xor_sync(0xffffffffu, val, o);
        if ((tid & 31) == 0) sm[tid >> 5] = val;
    }
    __syncthreads();
    if (tid == 0) {
        float tot = 0.f;
        #pragma unroll
        for (int j = 0; j < 8; j++) tot += sm[j];
        out[b] = tot + bf[0];
    }
}

// ---------------- host orchestration ----------------------------------------
extern "C" void kernel_launch(void* const* d_in, const int* in_sizes, int n_in,
                              void* d_out, int out_size)
{
    const float* x      = (const float*)d_in[0];
    const float* Wp     = (const float*)d_in[1];
    const float* bp     = (const float*)d_in[2];
    const float* W_in   = (const float*)d_in[3];
    const float* conv_w = (const float*)d_in[4];
    const float* conv_b = (const float*)d_in[5];
    const float* W_x    = (const float*)d_in[6];
    const float* W_dt   = (const float*)d_in[7];
    const float* b_dt   = (const float*)d_in[8];
    const float* A_log  = (const float*)d_in[9];
    const float* Dp     = (const float*)d_in[10];
    const float* W_out  = (const float*)d_in[11];
    const float* ln_g   = (const float*)d_in[12];
    const float* ln_b   = (const float*)d_in[13];
    const float* Wf     = (const float*)d_in[14];
    const float* bf     = (const float*)d_in[15];
    float* out = (float*)d_out;

    float *h, *xz, *xc, *xdbl, *dtb, *y, *ob;
    cudaGetSymbolAddress((void**)&h,    g_h);
    cudaGetSymbolAddress((void**)&xz,   g_xz);
    cudaGetSymbolAddress((void**)&xc,   g_xc);
    cudaGetSymbolAddress((void**)&xdbl, g_xdbl);
    cudaGetSymbolAddress((void**)&dtb,  g_dt);
    cudaGetSymbolAddress((void**)&y,    g_y);
    cudaGetSymbolAddress((void**)&ob,   g_ob);

    // input projection: h = x @ Wp^T + bp   (M=8192, N=256, K=64)
    gemm2_kernel<128,64,16,8,4,0,false><<<dim3(D_MODEL/64, BL/128), 256>>>(
        x, IN_DIM, Wp, IN_DIM, bp, h, D_MODEL, BL, D_MODEL, IN_DIM);

    for (int l = 0; l < N_LAYERS; l++) {
        const float* Wi = W_in  + (long)l * 2*D_INNER * D_MODEL;
        const float* cw = conv_w + (long)l * D_INNER * D_CONV;
        const float* cb = conv_b + (long)l * D_INNER;
        const float* Wx = W_x   + (long)l * 48 * D_INNER;
        const float* Wd = W_dt  + (long)l * D_INNER * DT_RANK;
        const float* bd = b_dt  + (long)l * D_INNER;
        const float* Al = A_log + (long)l * D_INNER * D_STATE;
        const float* Dl = Dp    + (long)l * D_INNER;
        const float* Wo = W_out + (long)l * D_MODEL * D_INNER;
        const float* lg = ln_g  + (long)l * D_MODEL;
        const float* lb = ln_b  + (long)l * D_MODEL;

        // xz = h @ W_in^T   (M=8192, N=1024, K=256) — 1024 blocks, 2 CTA/SM
        gemm2_kernel<128,64,16,8,4,0,false><<<dim3(1024/64, BL/128), 256>>>(
            h, D_MODEL, Wi, D_MODEL, nullptr, xz, 2*D_INNER,
            BL, 2*D_INNER, D_MODEL);

        // xc = silu(conv(xh) + cb), float4 over d
        conv_silu_kernel<<<BL*128/256, 256>>>(xz, cw, cb, xc);

        // x_dbl = xc @ W_x^T  (N=48, K=512) — BM=32: 256 blocks
        gemm2_kernel<32,64,16,4,4,0,true><<<dim3(1, BL/32), 128>>>(
            xc, D_INNER, Wx, D_INNER, nullptr, xdbl, 48, BL, 48, D_INNER);

        // dt = softplus(dtr @ W_dt^T + b_dt)   (N=512, K=16)
        gemm2_kernel<128,64,16,8,4,1,false><<<dim3(D_INNER/64, BL/128), 256>>>(
            xdbl, 48, Wd, DT_RANK, bd, dtb, D_INNER, BL, D_INNER, DT_RANK);

        // selective scan + gate
        scan3_kernel<<<dim3(D_INNER/16, BATCH), 64>>>(
            xdbl, dtb, xc, xz, Al, Dl, y);

        // out = y @ W_out^T  (N=256, K=512)
        gemm2_kernel<128,64,16,8,4,0,false><<<dim3(D_MODEL/64, BL/128), 256>>>(
            y, D_INNER, Wo, D_INNER, nullptr, ob, D_MODEL, BL, D_MODEL, D_INNER);

        // h = layernorm(out)
        ln_kernel<<<BL, 256>>>(ob, lg, lb, h);
    }

    final_kernel<<<BATCH, 1024>>>(h, Wf, bf, out);
}